// round 3
// baseline (speedup 1.0000x reference)
#include <cuda_runtime.h>
#include <cstdint>

// Problem dims
#define TT    512
#define BB    32
#define DD    512
#define HH    512
#define FEAT  2048
#define G4H   2048   // 4*H

// Output layout (fp32, tuple order: out, h_n, c_n, x, lens_s)
#define OUT_OFF  0
#define HN_OFF   16777216
#define CN_OFF   (16777216 + 32768)
#define X_OFF    (16777216 + 65536)
#define LENS_OFF (X_OFF + 8388608)

#define GSZ       (512*32*2048)        // per-direction G size (floats)
#define NCTA_SCAN 128
#define SCAN_SMEM ((16384 + 32*516) * 4)

// ---------------- device scratch (static globals: no allocations allowed) ---
__device__ float    g_G[2 * GSZ];          // input-gate preactivations, both dirs (268MB)
__device__ float    g_hbuf[4 * 16384];     // [dir][pingpong][32][512]
__device__ int      g_order[BB];
__device__ int      g_lens[BB];
__device__ unsigned g_bar;

// ---------------- reset / sort kernel --------------------------------------
__global__ void k_reset(const int* __restrict__ seq_lens,
                        const float* __restrict__ h0,
                        float* __restrict__ out) {
    int tid = threadIdx.x;
    if (tid == 0) {
        // stable argsort of -seq_lens: descending len, ties -> smaller index first
        unsigned used = 0u;
        for (int pos = 0; pos < BB; pos++) {
            int best = -1, bl = -1;
            for (int i = 0; i < BB; i++) {
                if (used & (1u << i)) continue;
                int L = seq_lens[i];
                if (L > bl) { bl = L; best = i; }
            }
            used |= 1u << best;
            g_order[pos] = best;
            g_lens[pos]  = bl;
            out[LENS_OFF + pos] = (float)bl;
        }
        g_bar = 0u;
    }
    // initialize h ping-pong buffer 0 with h0 (both directions)
    for (int i = tid; i < 2 * 16384; i += blockDim.x) {
        int dir = i >> 14;
        int r   = i & 16383;
        g_hbuf[(dir * 2 + 0) * 16384 + r] = h0[i];
    }
}

// ---------------- GEMM1: x[t,j,:] = mask * (cnn[lookup[order[j],t]] @ fc_w^T + fc_b)
// tiles: 64 rows (t within one j) x 64 cols, K-tiles of 16, 256 threads, 4x4/thread
__global__ void __launch_bounds__(256) k_gemm1(
    const float* __restrict__ cnn, const float* __restrict__ fcw,
    const float* __restrict__ fcb, const int* __restrict__ lookup,
    float* __restrict__ xout) {
    __shared__ float As[16][68];
    __shared__ float Bs[16][68];
    __shared__ int   simg[64];

    int j  = blockIdx.z;
    int t0 = blockIdx.y * 64;
    int n0 = blockIdx.x * 64;
    int tid = threadIdx.x;
    int len = g_lens[j];

    if (t0 >= len) {
        // fully masked tile: write zeros
        for (int i = tid; i < 1024; i += 256) {
            int r  = i >> 4;
            int cc = (i & 15) * 4;
            int t  = t0 + r;
            float4 z = make_float4(0.f, 0.f, 0.f, 0.f);
            *(float4*)&xout[((size_t)t * BB + j) * DD + n0 + cc] = z;
        }
        return;
    }
    int ord = g_order[j];
    if (tid < 64) simg[tid] = lookup[ord * TT + t0 + tid];
    __syncthreads();

    float acc[4][4];
#pragma unroll
    for (int a = 0; a < 4; a++)
#pragma unroll
        for (int bI = 0; bI < 4; bI++) acc[a][bI] = 0.f;

    int tx = tid & 15, ty = tid >> 4;   // output: rows ty*4.., cols tx*4..
    int lr = tid >> 2;                  // load row 0..63
    int lc = (tid & 3) * 4;             // load k-offset {0,4,8,12}

    for (int kt = 0; kt < FEAT; kt += 16) {
        float4 av = *(const float4*)&cnn[(size_t)simg[lr] * FEAT + kt + lc];
        float4 bv = *(const float4*)&fcw[(size_t)(n0 + lr) * FEAT + kt + lc];
        __syncthreads();
        As[lc + 0][lr] = av.x; As[lc + 1][lr] = av.y; As[lc + 2][lr] = av.z; As[lc + 3][lr] = av.w;
        Bs[lc + 0][lr] = bv.x; Bs[lc + 1][lr] = bv.y; Bs[lc + 2][lr] = bv.z; Bs[lc + 3][lr] = bv.w;
        __syncthreads();
#pragma unroll
        for (int kk = 0; kk < 16; kk++) {
            float4 a4 = *(const float4*)&As[kk][ty * 4];
            float4 b4 = *(const float4*)&Bs[kk][tx * 4];
            acc[0][0] += a4.x * b4.x; acc[0][1] += a4.x * b4.y; acc[0][2] += a4.x * b4.z; acc[0][3] += a4.x * b4.w;
            acc[1][0] += a4.y * b4.x; acc[1][1] += a4.y * b4.y; acc[1][2] += a4.y * b4.z; acc[1][3] += a4.y * b4.w;
            acc[2][0] += a4.z * b4.x; acc[2][1] += a4.z * b4.y; acc[2][2] += a4.z * b4.z; acc[2][3] += a4.z * b4.w;
            acc[3][0] += a4.w * b4.x; acc[3][1] += a4.w * b4.y; acc[3][2] += a4.w * b4.z; acc[3][3] += a4.w * b4.w;
        }
    }
    float bb0 = fcb[n0 + tx * 4 + 0];
    float bb1 = fcb[n0 + tx * 4 + 1];
    float bb2 = fcb[n0 + tx * 4 + 2];
    float bb3 = fcb[n0 + tx * 4 + 3];
#pragma unroll
    for (int mi = 0; mi < 4; mi++) {
        int t = t0 + ty * 4 + mi;
        bool v = (t < len);
        float4 o;
        o.x = v ? acc[mi][0] + bb0 : 0.f;
        o.y = v ? acc[mi][1] + bb1 : 0.f;
        o.z = v ? acc[mi][2] + bb2 : 0.f;
        o.w = v ? acc[mi][3] + bb3 : 0.f;
        *(float4*)&xout[((size_t)t * BB + j) * DD + n0 + tx * 4] = o;
    }
}

// ---------------- GEMM2: G[dir][j,t,:] = x[t,j,:] @ w_ih[dir]^T -----------
__global__ void __launch_bounds__(256) k_gemm2(
    const float* __restrict__ x, const float* __restrict__ wihf,
    const float* __restrict__ wihb) {
    __shared__ float As[16][68];
    __shared__ float Bs[16][68];

    int dir = blockIdx.z;
    int j   = blockIdx.y >> 3;
    int t0  = (blockIdx.y & 7) * 64;
    int n0  = blockIdx.x * 64;
    int tid = threadIdx.x;
    int len = g_lens[j];
    if (t0 >= len) return;  // never read by the scan

    const float* wih = dir ? wihb : wihf;
    float acc[4][4];
#pragma unroll
    for (int a = 0; a < 4; a++)
#pragma unroll
        for (int bI = 0; bI < 4; bI++) acc[a][bI] = 0.f;

    int tx = tid & 15, ty = tid >> 4;
    int lr = tid >> 2;
    int lc = (tid & 3) * 4;

    for (int kt = 0; kt < DD; kt += 16) {
        int t = t0 + lr;
        float4 av = *(const float4*)&x[((size_t)t * BB + j) * DD + kt + lc];
        float4 bv = *(const float4*)&wih[(size_t)(n0 + lr) * DD + kt + lc];
        __syncthreads();
        As[lc + 0][lr] = av.x; As[lc + 1][lr] = av.y; As[lc + 2][lr] = av.z; As[lc + 3][lr] = av.w;
        Bs[lc + 0][lr] = bv.x; Bs[lc + 1][lr] = bv.y; Bs[lc + 2][lr] = bv.z; Bs[lc + 3][lr] = bv.w;
        __syncthreads();
#pragma unroll
        for (int kk = 0; kk < 16; kk++) {
            float4 a4 = *(const float4*)&As[kk][ty * 4];
            float4 b4 = *(const float4*)&Bs[kk][tx * 4];
            acc[0][0] += a4.x * b4.x; acc[0][1] += a4.x * b4.y; acc[0][2] += a4.x * b4.z; acc[0][3] += a4.x * b4.w;
            acc[1][0] += a4.y * b4.x; acc[1][1] += a4.y * b4.y; acc[1][2] += a4.y * b4.z; acc[1][3] += a4.y * b4.w;
            acc[2][0] += a4.z * b4.x; acc[2][1] += a4.z * b4.y; acc[2][2] += a4.z * b4.z; acc[2][3] += a4.z * b4.w;
            acc[3][0] += a4.w * b4.x; acc[3][1] += a4.w * b4.y; acc[3][2] += a4.w * b4.z; acc[3][3] += a4.w * b4.w;
        }
    }
    float* Gd = g_G + (size_t)dir * GSZ;
#pragma unroll
    for (int mi = 0; mi < 4; mi++) {
        int t = t0 + ty * 4 + mi;
        float4 o = make_float4(acc[mi][0], acc[mi][1], acc[mi][2], acc[mi][3]);
        *(float4*)&Gd[((size_t)j * TT + t) * G4H + n0 + tx * 4] = o;
    }
}

// ---------------- persistent scan kernel -----------------------------------
__device__ __forceinline__ void grid_sync_step(int step) {
    __syncthreads();
    if (threadIdx.x == 0) {
        __threadfence();
        atomicAdd(&g_bar, 1u);
        unsigned target = (unsigned)(NCTA_SCAN * (step + 1));
        while (*(volatile unsigned*)&g_bar < target) { __nanosleep(32); }
    }
    __syncthreads();
}

__global__ void __launch_bounds__(256, 1) k_scan(
    const float* __restrict__ c0,
    const float* __restrict__ whhf, const float* __restrict__ whhb,
    const float* __restrict__ bihf, const float* __restrict__ bhhf,
    const float* __restrict__ bihb, const float* __restrict__ bhhb,
    float* __restrict__ out) {
    extern __shared__ float sm[];
    float* w_s = sm;            // [4 gates][8 hc][512 k] = 16384 floats
    float* h_s = sm + 16384;    // [32 b][516 padded]     = 16512 floats

    int bid   = blockIdx.x;
    int dir   = bid >> 6;
    int ctad  = bid & 63;
    int hcb   = ctad * 8;
    int tid   = threadIdx.x;
    int wp    = tid >> 5;       // warp 0..7 -> hc local
    int lane  = tid & 31;       // lane = sorted batch index b
    int hc    = hcb + wp;
    int b     = lane;

    const float* whh = dir ? whhb : whhf;
    // load this CTA's w_hh slice: rows {g*512 + hcb..hcb+7}
    for (int i = tid; i < 4096; i += 256) {        // i indexes float4
        int g   = i >> 10;
        int rem = i & 1023;
        int hcl = rem >> 7;
        int k   = (rem & 127) * 4;
        int gc  = g * HH + hcb + hcl;
        *(float4*)&w_s[(g * 8 + hcl) * 512 + k] =
            *(const float4*)&whh[(size_t)gc * HH + k];
    }

    int   len = g_lens[b];
    float bias0, bias1, bias2, bias3;
    {
        const float* bih = dir ? bihb : bihf;
        const float* bhh = dir ? bhhb : bhhf;
        bias0 = bih[0 * HH + hc] + bhh[0 * HH + hc];
        bias1 = bih[1 * HH + hc] + bhh[1 * HH + hc];
        bias2 = bih[2 * HH + hc] + bhh[2 * HH + hc];
        bias3 = bih[3 * HH + hc] + bhh[3 * HH + hc];
    }
    float creg = c0[dir * 16384 + b * HH + hc];
    float hreg = g_hbuf[(dir * 2 + 0) * 16384 + b * HH + hc];
    const float* Gd = g_G + (size_t)dir * GSZ;

    const float4* w0 = (const float4*)&w_s[(0 * 8 + wp) * 512];
    const float4* w1 = (const float4*)&w_s[(1 * 8 + wp) * 512];
    const float4* w2 = (const float4*)&w_s[(2 * 8 + wp) * 512];
    const float4* w3 = (const float4*)&w_s[(3 * 8 + wp) * 512];
    const float4* hv4 = (const float4*)&h_s[b * 516];

    for (int s = 0; s < TT; s++) {
        int p = s & 1;
        // stage h (written by all CTAs last step) into smem; L2-coherent loads
        const float* hin = &g_hbuf[(dir * 2 + p) * 16384];
        for (int i = tid; i < 4096; i += 256) {
            float4 v = __ldcg((const float4*)&hin[i * 4]);
            int bb = i >> 7;
            int kk = (i & 127) * 4;
            *(float4*)&h_s[bb * 516 + kk] = v;
        }
        __syncthreads();

        bool  active = (s < len);
        int   tt     = dir ? (len - 1 - s) : s;
        float gp0 = 0.f, gp1 = 0.f, gp2 = 0.f, gp3 = 0.f;
        if (active) {
            size_t base = ((size_t)b * TT + tt) * G4H + hc;
            gp0 = Gd[base + 0 * HH];
            gp1 = Gd[base + 1 * HH];
            gp2 = Gd[base + 2 * HH];
            gp3 = Gd[base + 3 * HH];
        }

        float a0 = 0.f, a1 = 0.f, a2 = 0.f, a3 = 0.f;
#pragma unroll 4
        for (int k4 = 0; k4 < 128; k4++) {
            float4 h4 = hv4[k4];
            float4 x0 = w0[k4]; a0 += h4.x * x0.x + h4.y * x0.y + h4.z * x0.z + h4.w * x0.w;
            float4 x1 = w1[k4]; a1 += h4.x * x1.x + h4.y * x1.y + h4.z * x1.z + h4.w * x1.w;
            float4 x2 = w2[k4]; a2 += h4.x * x2.x + h4.y * x2.y + h4.z * x2.z + h4.w * x2.w;
            float4 x3 = w3[k4]; a3 += h4.x * x3.x + h4.y * x3.y + h4.z * x3.z + h4.w * x3.w;
        }
        float gi = a0 + gp0 + bias0;
        float gf = a1 + gp1 + bias1;
        float gg = a2 + gp2 + bias2;
        float go = a3 + gp3 + bias3;
        float i_ = 1.f / (1.f + __expf(-gi));
        float f_ = 1.f / (1.f + __expf(-gf));
        float g_ = tanhf(gg);
        float o_ = 1.f / (1.f + __expf(-go));
        float cn = f_ * creg + i_ * g_;
        float hn = o_ * tanhf(cn);

        if (dir == 0) {
            out[OUT_OFF + ((size_t)s * BB + b) * 1024 + hc] = active ? hn : 0.f;
        } else {
            int tw = active ? (len - 1 - s) : s;
            out[OUT_OFF + ((size_t)tw * BB + b) * 1024 + 512 + hc] = active ? hn : 0.f;
        }
        if (active) { creg = cn; hreg = hn; }

        g_hbuf[(dir * 2 + (1 - p)) * 16384 + b * HH + hc] = hreg;
        grid_sync_step(s);
    }
    out[HN_OFF + dir * 16384 + b * HH + hc] = hreg;
    out[CN_OFF + dir * 16384 + b * HH + hc] = creg;
}

// ---------------- launcher --------------------------------------------------
extern "C" void kernel_launch(void* const* d_in, const int* in_sizes, int n_in,
                              void* d_out, int out_size) {
    const float* cnn  = (const float*)d_in[0];
    const float* fcw  = (const float*)d_in[1];
    const float* fcb  = (const float*)d_in[2];
    const float* h0   = (const float*)d_in[3];
    const float* c0   = (const float*)d_in[4];
    const float* wihf = (const float*)d_in[5];
    const float* whhf = (const float*)d_in[6];
    const float* bihf = (const float*)d_in[7];
    const float* bhhf = (const float*)d_in[8];
    const float* wihb = (const float*)d_in[9];
    const float* whhb = (const float*)d_in[10];
    const float* bihb = (const float*)d_in[11];
    const float* bhhb = (const float*)d_in[12];
    const int* seq_lens = (const int*)d_in[13];
    const int* lookup   = (const int*)d_in[14];
    float* out = (float*)d_out;

    cudaFuncSetAttribute(k_scan, cudaFuncAttributeMaxDynamicSharedMemorySize,
                         SCAN_SMEM);

    k_reset<<<1, 256>>>(seq_lens, h0, out);
    k_gemm1<<<dim3(8, 8, 32), 256>>>(cnn, fcw, fcb, lookup, out + X_OFF);
    k_gemm2<<<dim3(32, 256, 2), 256>>>(out + X_OFF, wihf, wihb);
    k_scan<<<NCTA_SCAN, 256, SCAN_SMEM>>>(c0, whhf, whhb, bihf, bhhf, bihb,
                                          bhhb, out);
}

// round 4
// speedup vs baseline: 1.1153x; 1.1153x over previous
#include <cuda_runtime.h>
#include <cstdint>

// Problem dims
#define TT    512
#define BB    32
#define DD    512
#define HH    512
#define FEAT  2048
#define G4H   2048   // 4*H

// Output layout (fp32, tuple order: out, h_n, c_n, x, lens_s)
#define OUT_OFF  0
#define HN_OFF   16777216
#define CN_OFF   (16777216 + 32768)
#define X_OFF    (16777216 + 65536)
#define LENS_OFF (X_OFF + 8388608)

#define GSZ       (512*32*2048)        // per-direction G size (floats)
#define NCTA_SCAN 128
#define SCAN_SMEM ((16384 + 32*516) * 4)

// ---------------- device scratch ---------------------------------------
__device__ float    g_G[2 * GSZ];          // input-gate preactivations (268MB)
__device__ float    g_hbuf[4 * 16384];     // [dir][pingpong][32][512]
__device__ int      g_order[BB];
__device__ int      g_lens[BB];
__device__ unsigned g_bar;

// ---------------- helpers ----------------------------------------------
__device__ __forceinline__ uint32_t f2tf32(float v) {
    uint32_t r;
    asm("cvt.rna.tf32.f32 %0, %1;" : "=r"(r) : "f"(v));
    return r;
}

__device__ __forceinline__ void mma_tf32(float4& c, const uint4& a,
                                         uint32_t b0, uint32_t b1) {
    asm volatile(
        "mma.sync.aligned.m16n8k8.row.col.f32.tf32.tf32.f32 "
        "{%0,%1,%2,%3}, {%4,%5,%6,%7}, {%8,%9}, {%0,%1,%2,%3};"
        : "+f"(c.x), "+f"(c.y), "+f"(c.z), "+f"(c.w)
        : "r"(a.x), "r"(a.y), "r"(a.z), "r"(a.w), "r"(b0), "r"(b1));
}

#define FMA2(acc, a, b) \
    asm("fma.rn.f32x2 %0, %1, %2, %0;" : "+l"(acc) : "l"(a), "l"(b))

__device__ __forceinline__ float sum2(unsigned long long v) {
    float lo, hi;
    asm("mov.b64 {%0,%1}, %2;" : "=f"(lo), "=f"(hi) : "l"(v));
    return lo + hi;
}

// ---------------- reset / sort kernel ----------------------------------
__global__ void k_reset(const int* __restrict__ seq_lens,
                        const float* __restrict__ h0,
                        float* __restrict__ out) {
    int tid = threadIdx.x;
    if (tid == 0) {
        unsigned used = 0u;
        for (int pos = 0; pos < BB; pos++) {
            int best = -1, bl = -1;
            for (int i = 0; i < BB; i++) {
                if (used & (1u << i)) continue;
                int L = seq_lens[i];
                if (L > bl) { bl = L; best = i; }
            }
            used |= 1u << best;
            g_order[pos] = best;
            g_lens[pos]  = bl;
            out[LENS_OFF + pos] = (float)bl;
        }
        g_bar = 0u;
    }
    for (int i = tid; i < 2 * 16384; i += blockDim.x) {
        int dir = i >> 14;
        int r   = i & 16383;
        g_hbuf[(dir * 2 + 0) * 16384 + r] = h0[i];
    }
}

// ================= 3xTF32 MMA GEMM kernels ==============================
// Tile 64(M) x 64(N) x 32(K), 128 threads (4 warps, 2x2), warp tile 32x32.
// Smem holds frag-native layouts: one LDS.128 per fragment, XOR(kq) swizzled.

// GEMM1: x[t,j,:] = mask * (cnn[lookup[order[j],t]] @ fc_w^T + fc_b)
__global__ void __launch_bounds__(128) k_gemm1(
    const float* __restrict__ cnn, const float* __restrict__ fcw,
    const float* __restrict__ fcb, const int* __restrict__ lookup,
    float* __restrict__ xout) {
    __shared__ float Ah[4][4][32][4];
    __shared__ float Al[4][4][32][4];
    __shared__ float Bs[4][8][32][4];   // [kq][n8][lane][b0h,b1h,b0l,b1l]
    __shared__ int   simg[64];

    int j   = blockIdx.z;
    int t0  = blockIdx.y * 64;
    int n0  = blockIdx.x * 64;
    int tid = threadIdx.x;
    int len = g_lens[j];

    if (t0 >= len) {
        for (int i = tid; i < 1024; i += 128) {
            int r  = i >> 4;
            int cc = (i & 15) * 4;
            int t  = t0 + r;
            *(float4*)&xout[((size_t)t * BB + j) * DD + n0 + cc] =
                make_float4(0.f, 0.f, 0.f, 0.f);
        }
        return;
    }
    int ord = g_order[j];
    if (tid < 64) simg[tid] = lookup[ord * TT + t0 + tid];
    __syncthreads();

    int lane = tid & 31;
    int w    = tid >> 5;
    int wm   = w >> 1, wn = w & 1;
    int g    = lane >> 2, tg = lane & 3;

    float4 c[2][4];
#pragma unroll
    for (int mi = 0; mi < 2; mi++)
#pragma unroll
        for (int ni = 0; ni < 4; ni++) c[mi][ni] = make_float4(0.f, 0.f, 0.f, 0.f);

    for (int k0 = 0; k0 < FEAT; k0 += 32) {
        float4 av[4], bv[4];
#pragma unroll
        for (int u = 0; u < 4; u++) {
            int i   = tid + 128 * u;
            int row = i >> 3, kc = (i & 7) << 2;
            av[u] = *(const float4*)&cnn[(size_t)simg[row] * FEAT + k0 + kc];
            bv[u] = *(const float4*)&fcw[(size_t)(n0 + row) * FEAT + k0 + kc];
        }
        __syncthreads();
#pragma unroll
        for (int u = 0; u < 4; u++) {
            int i   = tid + 128 * u;
            int row = i >> 3, kc = (i & 7) << 2;
            float va[4] = {av[u].x, av[u].y, av[u].z, av[u].w};
            float vb[4] = {bv[u].x, bv[u].y, bv[u].z, bv[u].w};
#pragma unroll
            for (int e = 0; e < 4; e++) {
                int k  = kc + e;
                int kq = k >> 3, kk = k & 7;
                int tig = kk & 3, ch = kk >> 2;
                // A scatter
                {
                    int gg = row & 7, rh = (row >> 3) & 1, m16 = row >> 4;
                    int ln = ((gg << 2) | tig) ^ kq;
                    int rg = rh | (ch << 1);
                    uint32_t hb = f2tf32(va[e]);
                    float hf = __uint_as_float(hb);
                    Ah[kq][m16][ln][rg] = hf;
                    Al[kq][m16][ln][rg] = __uint_as_float(f2tf32(va[e] - hf));
                }
                // B scatter
                {
                    int gg = row & 7, n8 = row >> 3;
                    int ln = ((gg << 2) | tig) ^ kq;
                    uint32_t hb = f2tf32(vb[e]);
                    float hf = __uint_as_float(hb);
                    Bs[kq][n8][ln][ch]     = hf;
                    Bs[kq][n8][ln][ch + 2] = __uint_as_float(f2tf32(vb[e] - hf));
                }
            }
        }
        __syncthreads();
#pragma unroll
        for (int kq = 0; kq < 4; kq++) {
            int sl = lane ^ kq;
            uint4 ahf[2], alf[2], bq[4];
#pragma unroll
            for (int mi = 0; mi < 2; mi++) {
                ahf[mi] = *(const uint4*)&Ah[kq][wm * 2 + mi][sl][0];
                alf[mi] = *(const uint4*)&Al[kq][wm * 2 + mi][sl][0];
            }
#pragma unroll
            for (int ni = 0; ni < 4; ni++)
                bq[ni] = *(const uint4*)&Bs[kq][wn * 4 + ni][sl][0];
#pragma unroll
            for (int mi = 0; mi < 2; mi++)
#pragma unroll
                for (int ni = 0; ni < 4; ni++) {
                    mma_tf32(c[mi][ni], ahf[mi], bq[ni].x, bq[ni].y);
                    mma_tf32(c[mi][ni], ahf[mi], bq[ni].z, bq[ni].w);
                    mma_tf32(c[mi][ni], alf[mi], bq[ni].x, bq[ni].y);
                }
        }
    }

    // store with bias + mask
#pragma unroll
    for (int mi = 0; mi < 2; mi++) {
#pragma unroll
        for (int ni = 0; ni < 4; ni++) {
            int cc  = n0 + wn * 32 + ni * 8 + tg * 2;
            float b0f = fcb[cc], b1f = fcb[cc + 1];
            int r0 = wm * 32 + mi * 16 + g;
            int t  = t0 + r0;
            float2 o;
            bool v = (t < len);
            o.x = v ? c[mi][ni].x + b0f : 0.f;
            o.y = v ? c[mi][ni].y + b1f : 0.f;
            *(float2*)&xout[((size_t)t * BB + j) * DD + cc] = o;
            int t2 = t + 8;
            bool v2 = (t2 < len);
            o.x = v2 ? c[mi][ni].z + b0f : 0.f;
            o.y = v2 ? c[mi][ni].w + b1f : 0.f;
            *(float2*)&xout[((size_t)t2 * BB + j) * DD + cc] = o;
        }
    }
}

// GEMM2: G[dir][j,t,:] = x[t,j,:] @ w_ih[dir]^T
__global__ void __launch_bounds__(128) k_gemm2(
    const float* __restrict__ x, const float* __restrict__ wihf,
    const float* __restrict__ wihb) {
    __shared__ float Ah[4][4][32][4];
    __shared__ float Al[4][4][32][4];
    __shared__ float Bs[4][8][32][4];

    int dir = blockIdx.z;
    int j   = blockIdx.y >> 3;
    int t0  = (blockIdx.y & 7) * 64;
    int n0  = blockIdx.x * 64;
    int tid = threadIdx.x;
    int len = g_lens[j];
    if (t0 >= len) return;

    const float* wih = dir ? wihb : wihf;
    int lane = tid & 31;
    int w    = tid >> 5;
    int wm   = w >> 1, wn = w & 1;
    int g    = lane >> 2, tg = lane & 3;

    float4 c[2][4];
#pragma unroll
    for (int mi = 0; mi < 2; mi++)
#pragma unroll
        for (int ni = 0; ni < 4; ni++) c[mi][ni] = make_float4(0.f, 0.f, 0.f, 0.f);

    for (int k0 = 0; k0 < DD; k0 += 32) {
        float4 av[4], bv[4];
#pragma unroll
        for (int u = 0; u < 4; u++) {
            int i   = tid + 128 * u;
            int row = i >> 3, kc = (i & 7) << 2;
            int t   = t0 + row;
            av[u] = *(const float4*)&x[((size_t)t * BB + j) * DD + k0 + kc];
            bv[u] = *(const float4*)&wih[(size_t)(n0 + row) * DD + k0 + kc];
        }
        __syncthreads();
#pragma unroll
        for (int u = 0; u < 4; u++) {
            int i   = tid + 128 * u;
            int row = i >> 3, kc = (i & 7) << 2;
            float va[4] = {av[u].x, av[u].y, av[u].z, av[u].w};
            float vb[4] = {bv[u].x, bv[u].y, bv[u].z, bv[u].w};
#pragma unroll
            for (int e = 0; e < 4; e++) {
                int k  = kc + e;
                int kq = k >> 3, kk = k & 7;
                int tig = kk & 3, ch = kk >> 2;
                {
                    int gg = row & 7, rh = (row >> 3) & 1, m16 = row >> 4;
                    int ln = ((gg << 2) | tig) ^ kq;
                    int rg = rh | (ch << 1);
                    uint32_t hb = f2tf32(va[e]);
                    float hf = __uint_as_float(hb);
                    Ah[kq][m16][ln][rg] = hf;
                    Al[kq][m16][ln][rg] = __uint_as_float(f2tf32(va[e] - hf));
                }
                {
                    int gg = row & 7, n8 = row >> 3;
                    int ln = ((gg << 2) | tig) ^ kq;
                    uint32_t hb = f2tf32(vb[e]);
                    float hf = __uint_as_float(hb);
                    Bs[kq][n8][ln][ch]     = hf;
                    Bs[kq][n8][ln][ch + 2] = __uint_as_float(f2tf32(vb[e] - hf));
                }
            }
        }
        __syncthreads();
#pragma unroll
        for (int kq = 0; kq < 4; kq++) {
            int sl = lane ^ kq;
            uint4 ahf[2], alf[2], bq[4];
#pragma unroll
            for (int mi = 0; mi < 2; mi++) {
                ahf[mi] = *(const uint4*)&Ah[kq][wm * 2 + mi][sl][0];
                alf[mi] = *(const uint4*)&Al[kq][wm * 2 + mi][sl][0];
            }
#pragma unroll
            for (int ni = 0; ni < 4; ni++)
                bq[ni] = *(const uint4*)&Bs[kq][wn * 4 + ni][sl][0];
#pragma unroll
            for (int mi = 0; mi < 2; mi++)
#pragma unroll
                for (int ni = 0; ni < 4; ni++) {
                    mma_tf32(c[mi][ni], ahf[mi], bq[ni].x, bq[ni].y);
                    mma_tf32(c[mi][ni], ahf[mi], bq[ni].z, bq[ni].w);
                    mma_tf32(c[mi][ni], alf[mi], bq[ni].x, bq[ni].y);
                }
        }
    }

    float* Gd = g_G + (size_t)dir * GSZ;
#pragma unroll
    for (int mi = 0; mi < 2; mi++) {
#pragma unroll
        for (int ni = 0; ni < 4; ni++) {
            int cc = n0 + wn * 32 + ni * 8 + tg * 2;
            int r0 = wm * 32 + mi * 16 + g;
            int t  = t0 + r0;
            *(float2*)&Gd[((size_t)j * TT + t) * G4H + cc] =
                make_float2(c[mi][ni].x, c[mi][ni].y);
            *(float2*)&Gd[((size_t)j * TT + t + 8) * G4H + cc] =
                make_float2(c[mi][ni].z, c[mi][ni].w);
        }
    }
}

// ---------------- persistent scan kernel --------------------------------
__device__ __forceinline__ void grid_sync_step(int step) {
    __syncthreads();
    if (threadIdx.x == 0) {
        __threadfence();
        atomicAdd(&g_bar, 1u);
        unsigned target = (unsigned)(NCTA_SCAN * (step + 1));
        while (*(volatile unsigned*)&g_bar < target) { __nanosleep(32); }
    }
    __syncthreads();
}

__global__ void __launch_bounds__(256, 1) k_scan(
    const float* __restrict__ c0,
    const float* __restrict__ whhf, const float* __restrict__ whhb,
    const float* __restrict__ bihf, const float* __restrict__ bhhf,
    const float* __restrict__ bihb, const float* __restrict__ bhhb,
    float* __restrict__ out) {
    extern __shared__ float sm[];
    float* w_s = sm;            // [4 gates][8 hc][512 k] = 16384 floats
    float* h_s = sm + 16384;    // [32 b][516 padded]

    int bid   = blockIdx.x;
    int dir   = bid >> 6;
    int ctad  = bid & 63;
    int hcb   = ctad * 8;
    int tid   = threadIdx.x;
    int wp    = tid >> 5;
    int lane  = tid & 31;
    int hc    = hcb + wp;
    int b     = lane;

    const float* whh = dir ? whhb : whhf;
    for (int i = tid; i < 4096; i += 256) {
        int gg  = i >> 10;
        int rem = i & 1023;
        int hcl = rem >> 7;
        int k   = (rem & 127) * 4;
        int gc  = gg * HH + hcb + hcl;
        *(float4*)&w_s[(gg * 8 + hcl) * 512 + k] =
            *(const float4*)&whh[(size_t)gc * HH + k];
    }

    int   len = g_lens[b];
    float bias0, bias1, bias2, bias3;
    {
        const float* bih = dir ? bihb : bihf;
        const float* bhh = dir ? bhhb : bhhf;
        bias0 = bih[0 * HH + hc] + bhh[0 * HH + hc];
        bias1 = bih[1 * HH + hc] + bhh[1 * HH + hc];
        bias2 = bih[2 * HH + hc] + bhh[2 * HH + hc];
        bias3 = bih[3 * HH + hc] + bhh[3 * HH + hc];
    }
    float creg = c0[dir * 16384 + b * HH + hc];
    float hreg = g_hbuf[(dir * 2 + 0) * 16384 + b * HH + hc];
    const float* Gd = g_G + (size_t)dir * GSZ;

    const ulonglong2* W0 = (const ulonglong2*)&w_s[(0 * 8 + wp) * 512];
    const ulonglong2* W1 = (const ulonglong2*)&w_s[(1 * 8 + wp) * 512];
    const ulonglong2* W2 = (const ulonglong2*)&w_s[(2 * 8 + wp) * 512];
    const ulonglong2* W3 = (const ulonglong2*)&w_s[(3 * 8 + wp) * 512];
    const ulonglong2* hv2 = (const ulonglong2*)&h_s[b * 516];

    for (int s = 0; s < TT; s++) {
        int p = s & 1;
        const float* hin = &g_hbuf[(dir * 2 + p) * 16384];
        for (int i = tid; i < 4096; i += 256) {
            float4 v = __ldcg((const float4*)&hin[i * 4]);
            int bb = i >> 7;
            int kk = (i & 127) * 4;
            *(float4*)&h_s[bb * 516 + kk] = v;
        }
        __syncthreads();

        bool  active = (s < len);
        int   tt     = dir ? (len - 1 - s) : s;
        float gp0 = 0.f, gp1 = 0.f, gp2 = 0.f, gp3 = 0.f;
        if (active) {
            size_t base = ((size_t)b * TT + tt) * G4H + hc;
            gp0 = Gd[base + 0 * HH];
            gp1 = Gd[base + 1 * HH];
            gp2 = Gd[base + 2 * HH];
            gp3 = Gd[base + 3 * HH];
        }

        unsigned long long s00 = 0, s01 = 0, s10 = 0, s11 = 0;
        unsigned long long s20 = 0, s21 = 0, s30 = 0, s31 = 0;
#pragma unroll 4
        for (int k4 = 0; k4 < 128; k4++) {
            ulonglong2 h2 = hv2[k4];
            ulonglong2 v0 = W0[k4]; FMA2(s00, h2.x, v0.x); FMA2(s01, h2.y, v0.y);
            ulonglong2 v1 = W1[k4]; FMA2(s10, h2.x, v1.x); FMA2(s11, h2.y, v1.y);
            ulonglong2 v2 = W2[k4]; FMA2(s20, h2.x, v2.x); FMA2(s21, h2.y, v2.y);
            ulonglong2 v3 = W3[k4]; FMA2(s30, h2.x, v3.x); FMA2(s31, h2.y, v3.y);
        }
        float gi = sum2(s00) + sum2(s01) + gp0 + bias0;
        float gf = sum2(s10) + sum2(s11) + gp1 + bias1;
        float gg = sum2(s20) + sum2(s21) + gp2 + bias2;
        float go = sum2(s30) + sum2(s31) + gp3 + bias3;
        float i_ = 1.f / (1.f + __expf(-gi));
        float f_ = 1.f / (1.f + __expf(-gf));
        float g_ = tanhf(gg);
        float o_ = 1.f / (1.f + __expf(-go));
        float cn = f_ * creg + i_ * g_;
        float hn = o_ * tanhf(cn);

        if (dir == 0) {
            out[OUT_OFF + ((size_t)s * BB + b) * 1024 + hc] = active ? hn : 0.f;
        } else {
            int tw = active ? (len - 1 - s) : s;
            out[OUT_OFF + ((size_t)tw * BB + b) * 1024 + 512 + hc] = active ? hn : 0.f;
        }
        if (active) { creg = cn; hreg = hn; }

        g_hbuf[(dir * 2 + (1 - p)) * 16384 + b * HH + hc] = hreg;
        grid_sync_step(s);
    }
    out[HN_OFF + dir * 16384 + b * HH + hc] = hreg;
    out[CN_OFF + dir * 16384 + b * HH + hc] = creg;
}

// ---------------- launcher ----------------------------------------------
extern "C" void kernel_launch(void* const* d_in, const int* in_sizes, int n_in,
                              void* d_out, int out_size) {
    const float* cnn  = (const float*)d_in[0];
    const float* fcw  = (const float*)d_in[1];
    const float* fcb  = (const float*)d_in[2];
    const float* h0   = (const float*)d_in[3];
    const float* c0   = (const float*)d_in[4];
    const float* wihf = (const float*)d_in[5];
    const float* whhf = (const float*)d_in[6];
    const float* bihf = (const float*)d_in[7];
    const float* bhhf = (const float*)d_in[8];
    const float* wihb = (const float*)d_in[9];
    const float* whhb = (const float*)d_in[10];
    const float* bihb = (const float*)d_in[11];
    const float* bhhb = (const float*)d_in[12];
    const int* seq_lens = (const int*)d_in[13];
    const int* lookup   = (const int*)d_in[14];
    float* out = (float*)d_out;

    cudaFuncSetAttribute(k_scan, cudaFuncAttributeMaxDynamicSharedMemorySize,
                         SCAN_SMEM);

    k_reset<<<1, 256>>>(seq_lens, h0, out);
    k_gemm1<<<dim3(8, 8, 32), 128>>>(cnn, fcw, fcb, lookup, out + X_OFF);
    k_gemm2<<<dim3(32, 256, 2), 128>>>(out + X_OFF, wihf, wihb);
    k_scan<<<NCTA_SCAN, 256, SCAN_SMEM>>>(c0, whhf, whhb, bihf, bhhf, bihb,
                                          bhhb, out);
}